// round 1
// baseline (speedup 1.0000x reference)
#include <cuda_runtime.h>
#include <math_constants.h>

#define NPTS 256
#define NBATCH 8

// Scratch for per-batch matched-cost sums (no device allocation allowed).
__device__ float g_batch_sum[NBATCH];

// One CTA per batch: shortest-augmenting-path LSA (Jonker-Volgenant style),
// equivalent to scipy.optimize.linear_sum_assignment. 256 threads = 1/column.
__global__ __launch_bounds__(NPTS) void emd_lsa_kernel(
    const float* __restrict__ pred, const float* __restrict__ label) {
    const int b = blockIdx.x;
    const int tid = threadIdx.x;

    __shared__ float px[NPTS], py[NPTS], pz[NPTS];
    __shared__ float lx[NPTS], ly[NPTS], lz[NPTS];
    __shared__ float u[NPTS], v[NPTS], shortest[NPTS];
    __shared__ int path[NPTS], row4col[NPTS], col4row[NPTS];
    __shared__ unsigned char SC[NPTS], SR[NPTS];
    __shared__ float wval[8];
    __shared__ int widx[8];
    __shared__ float s_minval;
    __shared__ int s_i, s_sink;

    // Load coordinates (SoA in smem for conflict-free broadcast reads)
    const float* P = pred + (size_t)b * NPTS * 3;
    const float* L = label + (size_t)b * NPTS * 3;
    px[tid] = P[tid * 3 + 0];
    py[tid] = P[tid * 3 + 1];
    pz[tid] = P[tid * 3 + 2];
    lx[tid] = L[tid * 3 + 0];
    ly[tid] = L[tid * 3 + 1];
    lz[tid] = L[tid * 3 + 2];
    u[tid] = 0.0f;
    v[tid] = 0.0f;
    row4col[tid] = -1;
    col4row[tid] = -1;
    __syncthreads();

    for (int cur_row = 0; cur_row < NPTS; ++cur_row) {
        // --- init augmenting search for this row ---
        shortest[tid] = CUDART_INF_F;
        SC[tid] = 0;
        SR[tid] = 0;
        if (tid == 0) {
            s_minval = 0.0f;
            s_i = cur_row;
            s_sink = -1;
        }
        __syncthreads();

        // --- Dijkstra-like scan: each step scans one column ---
        while (true) {
            const int i = s_i;
            const float mv = s_minval;
            if (tid == i) SR[tid] = 1;

            float val = CUDART_INF_F;
            if (!SC[tid]) {
                // cost(i, tid) computed on the fly (3D Euclidean)
                float dx = px[i] - lx[tid];
                float dy = py[i] - ly[tid];
                float dz = pz[i] - lz[tid];
                float c = sqrtf(dx * dx + dy * dy + dz * dz);
                float r = mv + c - u[i] - v[tid];
                if (r < shortest[tid]) {
                    shortest[tid] = r;
                    path[tid] = i;
                }
                val = shortest[tid];
            }

            // block argmin over unscanned columns (warp shfl + 8-way scalar)
            float bv = val;
            int bi = tid;
#pragma unroll
            for (int off = 16; off > 0; off >>= 1) {
                float ov = __shfl_down_sync(0xffffffffu, bv, off);
                int oi = __shfl_down_sync(0xffffffffu, bi, off);
                if (ov < bv) { bv = ov; bi = oi; }
            }
            if ((tid & 31) == 0) {
                wval[tid >> 5] = bv;
                widx[tid >> 5] = bi;
            }
            __syncthreads();

            if (tid == 0) {
                float best = wval[0];
                int bj = widx[0];
#pragma unroll
                for (int w = 1; w < 8; ++w)
                    if (wval[w] < best) { best = wval[w]; bj = widx[w]; }
                s_minval = best;
                SC[bj] = 1;
                if (row4col[bj] < 0) s_sink = bj;
                else s_i = row4col[bj];
            }
            __syncthreads();
            if (s_sink >= 0) break;
        }

        // --- dual variable update (parallel over rows/cols) ---
        const float mv = s_minval;
        if (tid == cur_row) {
            u[tid] += mv;
        } else if (SR[tid]) {
            u[tid] += mv - shortest[col4row[tid]];
        }
        if (SC[tid]) v[tid] -= mv - shortest[tid];
        __syncthreads();  // protect col4row/row4col reads from augment writes

        // --- augment along alternating path (short serial walk) ---
        if (tid == 0) {
            int j = s_sink;
            while (true) {
                int i = path[j];
                row4col[j] = i;
                int nj = col4row[i];
                col4row[i] = j;
                j = nj;
                if (i == cur_row) break;
            }
        }
        __syncthreads();
    }

    // --- matched distance per row, exact recompute from inputs ---
    {
        int j = col4row[tid];
        float dx = px[tid] - lx[j];
        float dy = py[tid] - ly[j];
        float dz = pz[tid] - lz[j];
        shortest[tid] = sqrtf(dx * dx + dy * dy + dz * dz);  // reuse as scratch
    }
    __syncthreads();
#pragma unroll
    for (int s = 128; s > 0; s >>= 1) {
        if (tid < s) shortest[tid] += shortest[tid + s];
        __syncthreads();
    }
    if (tid == 0) g_batch_sum[b] = shortest[0];
}

// Deterministic fixed-order final reduction (no float atomics).
__global__ void emd_reduce_kernel(float* __restrict__ out) {
    float s = 0.0f;
#pragma unroll
    for (int b = 0; b < NBATCH; ++b) s += g_batch_sum[b];
    out[0] = s / (float)(NBATCH * NPTS);
}

extern "C" void kernel_launch(void* const* d_in, const int* in_sizes, int n_in,
                              void* d_out, int out_size) {
    const float* pred = (const float*)d_in[0];
    const float* label = (const float*)d_in[1];
    float* out = (float*)d_out;
    emd_lsa_kernel<<<NBATCH, NPTS>>>(pred, label);
    emd_reduce_kernel<<<1, 1>>>(out);
}

// round 2
// speedup vs baseline: 2.5675x; 2.5675x over previous
#include <cuda_runtime.h>
#include <math_constants.h>

#define NPTS 256
#define NBATCH 8

// Per-batch matched-cost sums (no device allocation allowed).
__device__ float g_batch_sum[NBATCH];

// Order-preserving float <-> uint maps (for REDUX.MIN on float keys).
__device__ __forceinline__ unsigned ford(float f) {
    unsigned u = __float_as_uint(f);
    return (u & 0x80000000u) ? ~u : (u | 0x80000000u);
}
__device__ __forceinline__ float funord(unsigned x) {
    unsigned u = (x & 0x80000000u) ? (x & 0x7fffffffu) : ~x;
    return __uint_as_float(u);
}

// One CTA per batch. Jonker-Volgenant: column reduction + greedy init, then
// shortest-augmenting-path for the remaining free rows. Thread tid owns
// column tid (v, shortest, path, SC in registers) and row tid (u, SR).
__global__ __launch_bounds__(NPTS) void emd_lsa_kernel(
    const float* __restrict__ pred, const float* __restrict__ label) {
    const int b = blockIdx.x;
    const int tid = threadIdx.x;
    const int lane = tid & 31;
    const int warp = tid >> 5;

    __shared__ float px[NPTS], py[NPTS], pz[NPTS];
    __shared__ float sx[NPTS], sy[NPTS], sz[NPTS];
    __shared__ float u_s[NPTS];            // mirror of u for arbitrary-index reads
    __shared__ int row4col_s[NPTS];        // col j -> row
    __shared__ int col4row_s[NPTS];        // row i -> col
    __shared__ float shortest_s[NPTS];     // published once per search
    __shared__ int path_s[NPTS];
    __shared__ int amin_s[NPTS];
    __shared__ unsigned long long wslot[2][8];  // double-buffered per-warp argmin

    // ---- load coords ----
    const float* P = pred + (size_t)b * NPTS * 3;
    const float* L = label + (size_t)b * NPTS * 3;
    px[tid] = P[tid * 3 + 0];
    py[tid] = P[tid * 3 + 1];
    pz[tid] = P[tid * 3 + 2];
    sx[tid] = L[tid * 3 + 0];
    sy[tid] = L[tid * 3 + 1];
    sz[tid] = L[tid * 3 + 2];
    row4col_s[tid] = -1;
    col4row_s[tid] = -1;
    u_s[tid] = 0.0f;
    __syncthreads();

    // own-column label coords cached in registers
    const float lxr = sx[tid], lyr = sy[tid], lzr = sz[tid];

    // ---- JV column reduction: v[j] = min_i c(i,j), remember argmin ----
    float v_reg = CUDART_INF_F;
    int varg = 0;
    for (int i = 0; i < NPTS; ++i) {
        float dx = px[i] - lxr, dy = py[i] - lyr, dz = pz[i] - lzr;
        float c = sqrtf(fmaf(dx, dx, fmaf(dy, dy, dz * dz)));
        if (c < v_reg) { v_reg = c; varg = i; }
    }
    amin_s[tid] = varg;
    __syncthreads();

    // ---- greedy initial matching (exact: reduced cost 0 on assigned pairs) ----
    if (tid == 0) {
        for (int j = 0; j < NPTS; ++j) {
            int i = amin_s[j];
            if (col4row_s[i] < 0) { col4row_s[i] = j; row4col_s[j] = i; }
        }
    }
    __syncthreads();

    float u_reg = 0.0f;

    // ---- augment the remaining free rows ----
    for (int cur = 0; cur < NPTS; ++cur) {
        if (col4row_s[cur] >= 0) continue;  // uniform smem read: no divergence

        float shortest_reg = CUDART_INF_F;
        int path_reg = 0;
        bool SC_reg = false;
        bool SR_reg = (tid == cur);
        int i = cur;
        float mv = 0.0f;
        int parity = 0;
        int sink = -1;

        while (true) {
            // relax column tid from row i
            const float u_i = u_s[i];
            float dx = px[i] - lxr, dy = py[i] - lyr, dz = pz[i] - lzr;
            float c = sqrtf(fmaf(dx, dx, fmaf(dy, dy, dz * dz)));
            float r = mv + c - u_i - v_reg;
            if (!SC_reg && r < shortest_reg) { shortest_reg = r; path_reg = i; }

            // warp argmin: REDUX on order-mapped bits, ballot elects leader
            unsigned key = SC_reg ? 0xffffffffu : ford(shortest_reg);
            unsigned m = __reduce_min_sync(0xffffffffu, key);
            unsigned ball = __ballot_sync(0xffffffffu, key == m);
            if (lane == __ffs(ball) - 1)
                wslot[parity][warp] =
                    ((unsigned long long)m << 32) | (unsigned)tid;
            __syncthreads();

            // all threads redundantly combine the 8 warp results
            unsigned long long best = wslot[parity][0];
#pragma unroll
            for (int w = 1; w < 8; ++w) {
                unsigned long long x = wslot[parity][w];
                if (x < best) best = x;
            }
            parity ^= 1;

            int bj = (int)(unsigned)best;
            mv = funord((unsigned)(best >> 32));
            if (tid == bj) SC_reg = true;

            int r4 = row4col_s[bj];
            if (r4 < 0) { sink = bj; break; }
            i = r4;
            if (tid == i) SR_reg = true;
        }

        // publish per-column search results for dual update + augment
        shortest_s[tid] = shortest_reg;
        path_s[tid] = path_reg;
        __syncthreads();

        // dual update (reads OLD col4row, so before augment)
        if (tid == cur) {
            u_reg += mv;
        } else if (SR_reg) {
            u_reg += mv - shortest_s[col4row_s[tid]];
        }
        if (SR_reg) u_s[tid] = u_reg;
        if (SC_reg) v_reg -= mv - shortest_reg;
        __syncthreads();

        // augment along alternating path (short serial walk)
        if (tid == 0) {
            int j = sink;
            while (true) {
                int ii = path_s[j];
                row4col_s[j] = ii;
                int nj = col4row_s[ii];
                col4row_s[ii] = j;
                j = nj;
                if (ii == cur) break;
            }
        }
        __syncthreads();
    }

    // ---- matched distance per row, exact recompute ----
    {
        int j = col4row_s[tid];
        float dx = px[tid] - sx[j];
        float dy = py[tid] - sy[j];
        float dz = pz[tid] - sz[j];
        shortest_s[tid] = sqrtf(fmaf(dx, dx, fmaf(dy, dy, dz * dz)));
    }
    __syncthreads();
#pragma unroll
    for (int s = 128; s > 0; s >>= 1) {
        if (tid < s) shortest_s[tid] += shortest_s[tid + s];
        __syncthreads();
    }
    if (tid == 0) g_batch_sum[b] = shortest_s[0];
}

// Deterministic fixed-order final reduction.
__global__ void emd_reduce_kernel(float* __restrict__ out) {
    float s = 0.0f;
#pragma unroll
    for (int bb = 0; bb < NBATCH; ++bb) s += g_batch_sum[bb];
    out[0] = s / (float)(NBATCH * NPTS);
}

extern "C" void kernel_launch(void* const* d_in, const int* in_sizes, int n_in,
                              void* d_out, int out_size) {
    const float* pred = (const float*)d_in[0];
    const float* label = (const float*)d_in[1];
    float* out = (float*)d_out;
    emd_lsa_kernel<<<NBATCH, NPTS>>>(pred, label);
    emd_reduce_kernel<<<1, 1>>>(out);
}